// round 7
// baseline (speedup 1.0000x reference)
#include <cuda_runtime.h>
#include <cstdint>

// Problem shape (fixed by reference setup_inputs)
#define B_   16
#define Y_   32
#define HW_  65536                 // H*W = 256*256
#define NPIX (B_ * HW_)            // 1048576
#define THREADS 256
#define NBLOCKS (NPIX / THREADS)   // 4096
#define DIST_IND 7.0f
#define ROW_BYTES (THREADS * 4)    // 1024 bytes per row per block
#define TILE_BYTES (Y_ * ROW_BYTES)// 32 KB

__device__ double g_partials[NBLOCKS];
__device__ unsigned int g_count = 0;

__device__ __forceinline__ uint32_t smem_u32(const void* p) {
    uint32_t a;
    asm("{ .reg .u64 t; cvta.to.shared.u64 t, %1; cvt.u32.u64 %0, t; }"
        : "=r"(a) : "l"(p));
    return a;
}

__global__ void __launch_bounds__(THREADS)
disturbance_loss_fused(const float* __restrict__ out, float* __restrict__ d_out) {
    __shared__ alignas(1024) float tile[Y_ * THREADS];   // 32 KB
    __shared__ alignas(8) uint64_t mbar;

    const int p0 = blockIdx.x * THREADS;     // first pixel of this block
    const int b  = p0 >> 16;
    const int hw = p0 & (HW_ - 1);
    const float* __restrict__ base = out + (size_t)b * (Y_ * HW_) + hw;

    const uint32_t mbar_a = smem_u32(&mbar);
    const uint32_t tile_a = smem_u32(tile);

    if (threadIdx.x == 0) {
        asm volatile("mbarrier.init.shared.b64 [%0], 1;" :: "r"(mbar_a) : "memory");
    }
    __syncthreads();

    if (threadIdx.x == 0) {
        asm volatile("mbarrier.arrive.expect_tx.shared.b64 _, [%0], %1;"
                     :: "r"(mbar_a), "r"((uint32_t)TILE_BYTES) : "memory");
#pragma unroll
        for (int y = 0; y < Y_; ++y) {
            asm volatile(
                "cp.async.bulk.shared::cta.global.mbarrier::complete_tx::bytes "
                "[%0], [%1], %2, [%3];"
                :: "r"(tile_a + y * ROW_BYTES),
                   "l"(base + (size_t)y * HW_),
                   "r"((uint32_t)ROW_BYTES),
                   "r"(mbar_a)
                : "memory");
        }
    }

    // Wait for the whole 32 KB tile (parity phase 0; barrier fresh per launch).
    {
        uint32_t done;
        asm volatile(
            "{\n\t"
            ".reg .pred p;\n\t"
            "mbarrier.try_wait.parity.acquire.cta.shared::cta.b64 p, [%1], 0;\n\t"
            "selp.b32 %0, 1, 0, p;\n\t"
            "}" : "=r"(done) : "r"(mbar_a) : "memory");
        if (!done) {
            asm volatile(
                "{\n\t"
                ".reg .pred P1;\n\t"
                "WL_%=:\n\t"
                "mbarrier.try_wait.parity.acquire.cta.shared::cta.b64 P1, [%0], 0, 0x989680;\n\t"
                "@P1 bra.uni WD_%=;\n\t"
                "bra.uni WL_%=;\n\t"
                "WD_%=:\n\t"
                "}" :: "r"(mbar_a) : "memory");
        }
    }

    // ---- streaming pass over SMEM column (conflict-free: lane t -> bank t) ----
    const int t = threadIdx.x;
    float a0 = 0.f, a1 = 0.f, a2 = 0.f, c0 = 0.f, c1 = 0.f, c2 = 0.f;
    float m1 = 0.f, m2 = 0.f, prev = 0.f;
#pragma unroll
    for (int y = 0; y < Y_; ++y) {
        const float u = tile[y * THREADS + t];
        if (y >= 2 && y <= Y_ - 2) {
            float d = u - prev;
            if (y & 1) m2 = fminf(m2, d); else m1 = fminf(m1, d);
        }
        if (y & 1) {
            c0 += u; c1 = fmaf((float)y, u, c1); c2 = fmaf(u, u, c2);
        } else {
            a0 += u; a1 = fmaf((float)y, u, a1); a2 = fmaf(u, u, a2);
        }
        prev = u;
    }
    const float T0 = a0 + c0, T1 = a1 + c1, T2 = a2 + c2;
    const float dmin = fminf(m1, m2);

    // f=0 unless some interior diff beats the -DIST_IND sentinel (~4e-7/elem).
    int   f = 0;
    float s0 = 0.f, s1 = 0.f, s2 = 0.f;
    if (__ballot_sync(0xFFFFFFFFu, dmin < -DIST_IND)) {
        // Rare slow path: exact first-occurrence argmin with prefix snapshots.
        float best = -DIST_IND;
        float q0 = 0.f, q1 = 0.f, q2 = 0.f, pv = 0.f;
#pragma unroll 1
        for (int y = 0; y < Y_; ++y) {
            float u = tile[y * THREADS + t];
            if (y >= 2 && y <= Y_ - 2) {
                float d = u - pv;
                if (d < best) { best = d; f = y; s0 = q0; s1 = q1; s2 = q2; }
            }
            q0 += u;
            q1 = fmaf((float)y, u, q1);
            q2 = fmaf(u, u, q2);
            pv = u;
        }
    }

    // ---- closed-form regression + residuals ----
    const float ff = (float)f;
    const int   m  = Y_ - f;

    const float n_b   = ff;
    const float sx_b  = (float)(f * (f - 1) / 2);
    const float sxx_b = (float)((f - 1) * f * (2 * f - 1) / 6);
    const float sy_b  = s0, sxy_b = s1, syy_b = s2;

    const float n_a   = (float)m;
    const float sx_a  = (float)(m * (m - 1) / 2);
    const float sxx_a = (float)((m - 1) * m * (2 * m - 1) / 6);
    const float sy_a  = T0 - s0;
    const float sxy_a = (T1 - s1) - ff * sy_a;
    const float syy_a = T2 - s2;

    float contrib = 0.f;
    {   // before
        float ns  = fmaxf(n_b, 1.0f);
        float cov = sxy_b - sx_b * sy_b / ns;
        float var = sxx_b - sx_b * sx_b / ns;
        float vs  = (var > 0.f) ? var : 1.f;
        float s   = fminf(fmaxf(cov / vs, 0.f), 2.f);
        float c   = (sy_b - s * sx_b) / ns;
        float res = syy_b - 2.f * s * sxy_b - 2.f * c * sy_b
                  + s * s * sxx_b + 2.f * s * c * sx_b + c * c * n_b;
        if (n_b >= 3.f) contrib += res;
    }
    {   // after
        float ns  = fmaxf(n_a, 1.0f);
        float cov = sxy_a - sx_a * sy_a / ns;
        float var = sxx_a - sx_a * sx_a / ns;
        float vs  = (var > 0.f) ? var : 1.f;
        float s   = fminf(fmaxf(cov / vs, 0.f), 2.f);
        float c   = (sy_a - s * sx_a) / ns;
        float res = syy_a - 2.f * s * sxy_a - 2.f * c * sy_a
                  + s * s * sxx_a + 2.f * s * c * sx_a + c * c * n_a;
        if (n_a >= 3.f) contrib += res;
    }

    // ---- deterministic in-block reduction ----
    const unsigned lane = threadIdx.x & 31u;
    const unsigned wid  = threadIdx.x >> 5;
    float w = contrib;
#pragma unroll
    for (int o = 16; o > 0; o >>= 1)
        w += __shfl_down_sync(0xFFFFFFFFu, w, o);

    __shared__ float warpsum[THREADS / 32];
    if (lane == 0) warpsum[wid] = w;
    __syncthreads();

    __shared__ bool is_last;
    if (wid == 0) {
        float s = (lane < THREADS / 32) ? warpsum[lane] : 0.f;
#pragma unroll
        for (int o = 4; o > 0; o >>= 1)
            s += __shfl_down_sync(0xFFFFFFFFu, s, o);
        if (lane == 0) {
            g_partials[blockIdx.x] = (double)s;
            __threadfence();
            unsigned done = atomicAdd(&g_count, 1u);
            is_last = (done == (unsigned)(NBLOCKS - 1));
        }
    }
    __syncthreads();

    // ---- last block sums all partials in fixed index order (deterministic) ----
    if (is_last) {
        __threadfence();
        double s = 0.0;
#pragma unroll
        for (int k = 0; k < NBLOCKS / THREADS; ++k)
            s += g_partials[threadIdx.x + k * THREADS];
#pragma unroll
        for (int o = 16; o > 0; o >>= 1)
            s += __shfl_down_sync(0xFFFFFFFFu, s, o);
        __shared__ double wsum[THREADS / 32];
        if (lane == 0) wsum[wid] = s;
        __syncthreads();
        if (wid == 0) {
            double u = (lane < THREADS / 32) ? wsum[lane] : 0.0;
#pragma unroll
            for (int o = 4; o > 0; o >>= 1)
                u += __shfl_down_sync(0xFFFFFFFFu, u, o);
            if (lane == 0) {
                d_out[0] = (float)(u / ((double)Y_ * (double)NPIX));
                g_count = 0;   // reset for next graph replay
            }
        }
    }
}

extern "C" void kernel_launch(void* const* d_in, const int* in_sizes, int n_in,
                              void* d_out, int out_size) {
    const float* out = (const float*)d_in[0];   // 'target' (d_in[1]) unused by reference
    (void)in_sizes; (void)n_in; (void)out_size;
    disturbance_loss_fused<<<NBLOCKS, THREADS>>>(out, (float*)d_out);
}

// round 8
// speedup vs baseline: 1.5000x; 1.5000x over previous
#include <cuda_runtime.h>
#include <cstdint>

// Problem shape (fixed by reference setup_inputs)
#define B_   16
#define Y_   32
#define HW_  65536                   // H*W
#define NPIX (B_ * HW_)              // 1048576
#define THREADS 256
#define TILE_PX 256                  // pixels per tile (one per thread)
#define NTILES (NPIX / TILE_PX)      // 4096
#define GRID 304                     // 2 blocks/SM x 152 SMs -> single wave
#define STAGES 3
#define ROW_BYTES (TILE_PX * 4)      // 1024 B contiguous per row
#define TILE_BYTES (Y_ * ROW_BYTES)  // 32 KB
#define SMEM_BYTES (1024 + STAGES * TILE_BYTES)   // barriers pad + 96 KB tiles
#define DIST_IND 7.0f

__device__ double g_partials[GRID];
__device__ unsigned int g_count = 0;

__device__ __forceinline__ uint32_t smem_u32(const void* p) {
    uint32_t a;
    asm("{ .reg .u64 t; cvta.to.shared.u64 t, %1; cvt.u32.u64 %0, t; }"
        : "=r"(a) : "l"(p));
    return a;
}

__device__ __forceinline__ void mbar_wait(uint32_t mbar_a, uint32_t parity) {
    uint32_t done;
    asm volatile(
        "{\n\t.reg .pred p;\n\t"
        "mbarrier.try_wait.parity.acquire.cta.shared::cta.b64 p, [%1], %2;\n\t"
        "selp.b32 %0, 1, 0, p;\n\t}"
        : "=r"(done) : "r"(mbar_a), "r"(parity) : "memory");
    if (!done) {
        asm volatile(
            "{\n\t.reg .pred P1;\n\t"
            "WL_%=:\n\t"
            "mbarrier.try_wait.parity.acquire.cta.shared::cta.b64 P1, [%0], %1, 0x989680;\n\t"
            "@P1 bra.uni WD_%=;\n\t"
            "bra.uni WL_%=;\n\t"
            "WD_%=:\n\t}"
            :: "r"(mbar_a), "r"(parity) : "memory");
    }
}

__global__ void __launch_bounds__(THREADS)
disturbance_loss_fused(const float* __restrict__ out, float* __restrict__ d_out) {
    extern __shared__ char smem_raw[];
    uint64_t* mbar  = (uint64_t*)smem_raw;            // STAGES barriers
    float*    tiles = (float*)(smem_raw + 1024);      // STAGES x 32 KB

    const uint32_t mbar_a = smem_u32(mbar);
    const uint32_t tile_a = smem_u32(tiles);
    const int t = threadIdx.x;

    if (t == 0) {
#pragma unroll
        for (int s = 0; s < STAGES; ++s)
            asm volatile("mbarrier.init.shared.b64 [%0], 1;"
                         :: "r"(mbar_a + s * 8) : "memory");
    }
    __syncthreads();

    const int bid = blockIdx.x;
    const int nt  = (NTILES - bid + GRID - 1) / GRID;   // 13 or 14 tiles

    // Issue one tile's 32 row copies into stage s (thread 0 only).
    auto issue_tile = [&](int j, int s) {
        const int T  = bid + j * GRID;          // strided tile assignment
        const int p0 = T * TILE_PX;
        const int b  = p0 >> 16;
        const int hw = p0 & (HW_ - 1);
        const float* gbase = out + (size_t)b * (Y_ * HW_) + hw;
        const uint32_t dst0 = tile_a + s * TILE_BYTES;
        asm volatile("mbarrier.arrive.expect_tx.shared.b64 _, [%0], %1;"
                     :: "r"(mbar_a + s * 8), "r"((uint32_t)TILE_BYTES) : "memory");
#pragma unroll
        for (int y = 0; y < Y_; ++y) {
            asm volatile(
                "cp.async.bulk.shared::cta.global.mbarrier::complete_tx::bytes "
                "[%0], [%1], %2, [%3];"
                :: "r"(dst0 + y * ROW_BYTES),
                   "l"(gbase + (size_t)y * HW_),
                   "r"((uint32_t)ROW_BYTES),
                   "r"(mbar_a + s * 8)
                : "memory");
        }
    };

    if (t == 0) {
        issue_tile(0, 0);
        if (nt > 1) issue_tile(1, 1);
        if (nt > 2) issue_tile(2, 2);
    }

    float contrib = 0.f;

    for (int j = 0; j < nt; ++j) {
        const int s = j % STAGES;
        mbar_wait(mbar_a + s * 8, (uint32_t)((j / STAGES) & 1));

        const float* tile = tiles + s * (Y_ * TILE_PX);

        // ---- per-pixel streaming pass over SMEM (lane t -> bank t, no conflicts) ----
        float a0 = 0.f, a1 = 0.f, a2 = 0.f, c0 = 0.f, c1 = 0.f, c2 = 0.f;
        float m1 = 0.f, m2 = 0.f, prev = 0.f;
#pragma unroll
        for (int y = 0; y < Y_; ++y) {
            const float u = tile[y * TILE_PX + t];
            if (y >= 2 && y <= Y_ - 2) {
                float d = u - prev;
                if (y & 1) m2 = fminf(m2, d); else m1 = fminf(m1, d);
            }
            if (y & 1) {
                c0 += u; c1 = fmaf((float)y, u, c1); c2 = fmaf(u, u, c2);
            } else {
                a0 += u; a1 = fmaf((float)y, u, a1); a2 = fmaf(u, u, a2);
            }
            prev = u;
        }
        const float T0 = a0 + c0, T1 = a1 + c1, T2 = a2 + c2;
        const float dmin = fminf(m1, m2);

        int   f = 0;
        float s0 = 0.f, s1 = 0.f, s2 = 0.f;
        if (__ballot_sync(0xFFFFFFFFu, dmin < -DIST_IND)) {
            // Rare slow path (~4e-7/elem): exact first-occurrence argmin.
            float best = -DIST_IND;
            float q0 = 0.f, q1 = 0.f, q2 = 0.f, pv = 0.f;
#pragma unroll 1
            for (int y = 0; y < Y_; ++y) {
                float u = tile[y * TILE_PX + t];
                if (y >= 2 && y <= Y_ - 2) {
                    float d = u - pv;
                    if (d < best) { best = d; f = y; s0 = q0; s1 = q1; s2 = q2; }
                }
                q0 += u;
                q1 = fmaf((float)y, u, q1);
                q2 = fmaf(u, u, q2);
                pv = u;
            }
        }

        // ---- closed-form regression + residuals ----
        const float ff = (float)f;
        const int   m  = Y_ - f;

        const float n_b   = ff;
        const float sx_b  = (float)(f * (f - 1) / 2);
        const float sxx_b = (float)((f - 1) * f * (2 * f - 1) / 6);
        const float sy_b  = s0, sxy_b = s1, syy_b = s2;

        const float n_a   = (float)m;
        const float sx_a  = (float)(m * (m - 1) / 2);
        const float sxx_a = (float)((m - 1) * m * (2 * m - 1) / 6);
        const float sy_a  = T0 - s0;
        const float sxy_a = (T1 - s1) - ff * sy_a;
        const float syy_a = T2 - s2;

        {   // before
            float ns  = fmaxf(n_b, 1.0f);
            float cov = sxy_b - sx_b * sy_b / ns;
            float var = sxx_b - sx_b * sx_b / ns;
            float vs  = (var > 0.f) ? var : 1.f;
            float sl  = fminf(fmaxf(cov / vs, 0.f), 2.f);
            float c   = (sy_b - sl * sx_b) / ns;
            float res = syy_b - 2.f * sl * sxy_b - 2.f * c * sy_b
                      + sl * sl * sxx_b + 2.f * sl * c * sx_b + c * c * n_b;
            if (n_b >= 3.f) contrib += res;
        }
        {   // after
            float ns  = fmaxf(n_a, 1.0f);
            float cov = sxy_a - sx_a * sy_a / ns;
            float var = sxx_a - sx_a * sx_a / ns;
            float vs  = (var > 0.f) ? var : 1.f;
            float sl  = fminf(fmaxf(cov / vs, 0.f), 2.f);
            float c   = (sy_a - sl * sx_a) / ns;
            float res = syy_a - 2.f * sl * sxy_a - 2.f * c * sy_a
                      + sl * sl * sxx_a + 2.f * sl * c * sx_a + c * c * n_a;
            if (n_a >= 3.f) contrib += res;
        }

        // All threads done reading stage s before refilling it.
        __syncthreads();
        if (t == 0 && j + STAGES < nt) issue_tile(j + STAGES, s);
    }

    // ---- deterministic in-block reduction ----
    const unsigned lane = threadIdx.x & 31u;
    const unsigned wid  = threadIdx.x >> 5;
    float w = contrib;
#pragma unroll
    for (int o = 16; o > 0; o >>= 1)
        w += __shfl_down_sync(0xFFFFFFFFu, w, o);

    __shared__ float warpsum[THREADS / 32];
    if (lane == 0) warpsum[wid] = w;
    __syncthreads();

    __shared__ bool is_last;
    if (wid == 0) {
        float x = (lane < THREADS / 32) ? warpsum[lane] : 0.f;
#pragma unroll
        for (int o = 4; o > 0; o >>= 1)
            x += __shfl_down_sync(0xFFFFFFFFu, x, o);
        if (lane == 0) {
            g_partials[bid] = (double)x;
            __threadfence();
            unsigned done = atomicAdd(&g_count, 1u);
            is_last = (done == (unsigned)(GRID - 1));
        }
    }
    __syncthreads();

    // ---- last block sums all partials in fixed index order (deterministic) ----
    if (is_last) {
        __threadfence();
        double sd = 0.0;
        for (int i = threadIdx.x; i < GRID; i += THREADS)
            sd += g_partials[i];
#pragma unroll
        for (int o = 16; o > 0; o >>= 1)
            sd += __shfl_down_sync(0xFFFFFFFFu, sd, o);
        __shared__ double wsum[THREADS / 32];
        if (lane == 0) wsum[wid] = sd;
        __syncthreads();
        if (wid == 0) {
            double u = (lane < THREADS / 32) ? wsum[lane] : 0.0;
#pragma unroll
            for (int o = 4; o > 0; o >>= 1)
                u += __shfl_down_sync(0xFFFFFFFFu, u, o);
            if (lane == 0) {
                d_out[0] = (float)(u / ((double)Y_ * (double)NPIX));
                g_count = 0;   // reset for next graph replay
            }
        }
    }
}

extern "C" void kernel_launch(void* const* d_in, const int* in_sizes, int n_in,
                              void* d_out, int out_size) {
    const float* out = (const float*)d_in[0];   // 'target' (d_in[1]) unused by reference
    (void)in_sizes; (void)n_in; (void)out_size;

    static bool configured = false;
    if (!configured) {
        cudaFuncSetAttribute(disturbance_loss_fused,
                             cudaFuncAttributeMaxDynamicSharedMemorySize, SMEM_BYTES);
        configured = true;
    }
    disturbance_loss_fused<<<GRID, THREADS, SMEM_BYTES>>>(out, (float*)d_out);
}